// round 12
// baseline (speedup 1.0000x reference)
#include <cuda_runtime.h>
#include <cuda_fp16.h>

// B=16, C=64, H=W=256, STRIDE=2, IN_KS=OUT_KS=3
#define HH 256
#define WW 256
#define HP 128
#define WP 128
#define TH 64              // output rows per block
#define NT 4               // tiles per plane
#define NTHR 512
#define CAN_H 66           // image rows R0-1 .. R0+64
#define CAN_WH 264         // halves per row (258 used; 528B, 16B-aligned stride)
#define PR_H 35            // prov rows I0-1 .. I0+33
#define PR_W 136           // ushort; cell j at index j+4, halos at 3 and 132

#define HNEG 0xFC00u           // half -inf
#define HNEG4 0xFC00FC00u

__device__ __forceinline__ unsigned hmax2u(unsigned a, unsigned b) {
    __half2 r = __hmax2(*(__half2*)&a, *(__half2*)&b);
    return *(unsigned*)&r;
}

__global__ __launch_bounds__(NTHR, 4)
void morph_unpool_dilate_kernel(const float* __restrict__ f,
                                const int*   __restrict__ prov,
                                float*       __restrict__ out)
{
    __shared__ __align__(16) unsigned short canvas[CAN_H][CAN_WH];
    __shared__ unsigned short               sprov[PR_H][PR_W];

    const int bid  = blockIdx.x;
    const int bc   = bid >> 2;            // plane (b*c)
    const int tile = bid & 3;
    const int R0   = tile * TH;
    const int I0   = tile * (TH / 2);
    const int tid  = threadIdx.x;

    const float4* fb4 = (const float4*)(f + (size_t)bc * (HP * WP));
    const int4*   pb4 = (const int4*)  (prov + (size_t)bc * (HP * WP));

    // ---- Phase 1a: fill canvas: half(0); out-of-plane rows: half(-inf) ----
    {
        uint4* c4 = (uint4*)&canvas[0][0];
        #pragma unroll
        for (int idx = tid; idx < CAN_H * (CAN_WH / 8); idx += NTHR) {
            int  row  = idx / (CAN_WH / 8);
            bool ninf = (tile == 0 && row == 0) ||
                        (tile == NT - 1 && row == CAN_H - 1);
            unsigned v = ninf ? HNEG4 : 0u;
            c4[idx] = make_uint4(v, v, v, v);
        }
    }

    // ---- Phase 1b: stage provenance as u16 (int4 loads, ushort4 stores) ----
    for (int idx = tid; idx < PR_H * 32; idx += NTHR) {
        int li = idx >> 5;                 // cell row i = I0-1+li
        int g  = idx & 31;
        int i  = I0 - 1 + li;
        ushort4 s = make_ushort4(0, 0, 0, 0);   // out-of-range sentinel
        if ((unsigned)i < HP) {
            int4 p = pb4[i * 32 + g];
            s = make_ushort4((unsigned short)p.x, (unsigned short)p.y,
                             (unsigned short)p.z, (unsigned short)p.w);
        }
        *(ushort4*)&sprov[li][(g << 2) + 4] = s;
    }
    if (tid < PR_H * 2) {                  // column halos
        int li = tid >> 1;
        if (tid & 1) sprov[li][132] = 0;        // j=128 (comparers have c>=254)
        else         sprov[li][3]   = 0xFFFF;   // j=-1  (comparers have c<=2)
    }
    __syncthreads();

    // ---- Phase 2a: -inf column borders (never scatter targets) ----
    if (tid < CAN_H * 2) {
        int r = tid >> 1;
        canvas[r][(tid & 1) ? 257 : 0] = (unsigned short)HNEG;
    }

    // ---- Phase 2b: race-free last-write-wins scatter (R3/R6 form, STS.16) ----
    // Cell (i,j) writes iff none of (i,j+1),(i+1,j-1),(i+1,j),(i+1,j+1)
    // (all higher linear index) targets the same pixel.
    for (int idx = tid; idx < (PR_H - 1) * 32; idx += NTHR) {
        int li = idx >> 5;
        int g  = idx & 31;
        int i  = I0 - 1 + li;
        if ((unsigned)i < HP) {
            int j = g << 2;
            ushort4 o  = *(const ushort4*)&sprov[li][j + 4];
            ushort4 bw = *(const ushort4*)&sprov[li + 1][j + 4];
            int rr = sprov[li][j + 8];
            int bl = sprov[li + 1][j + 3];
            int br = sprov[li + 1][j + 8];
            float4 fv = fb4[i * 32 + g];
            int t0 = o.x,  t1 = o.y,  t2 = o.z,  t3 = o.w;
            int b0 = bw.x, b1 = bw.y, b2 = bw.z, b3 = bw.w;

            #define SCATTER(t, n1, n2, n3, n4, val)                          \
            {                                                                \
                bool sup = ((n1) == (t)) | ((n2) == (t)) |                   \
                           ((n3) == (t)) | ((n4) == (t));                    \
                int lr = ((t) >> 8) - R0 + 1;                                \
                if (!sup && (unsigned)lr < CAN_H)                            \
                    canvas[lr][((t) & 255) + 1] =                            \
                        __half_as_ushort(__float2half_rn(val));              \
            }
            SCATTER(t0, t1, bl, b0, b1, fv.x);
            SCATTER(t1, t2, b0, b1, b2, fv.y);
            SCATTER(t2, t3, b1, b2, b3, fv.z);
            SCATTER(t3, rr, b2, b3, br, fv.w);
            #undef SCATTER
        }
    }
    __syncthreads();

    // ---- Phase 3: 3x3 max; dense LDS.128 rows, seam via shfl of A.x,
    //      vertical HMAX2 then PRMT horizontal, one st.global.v8.f32/row ----
    const int g    = tid & 31;
    const int cb   = g << 3;               // output col base; canvas idx cb..cb+9
    const int base = (tid >> 5) << 2;      // warp 0..15 -> rows 0..60
    float* ob = out + (size_t)bc * (HH * WW) + (size_t)(R0 + base) * WW + cb;

    auto load_row = [&](int r, uint4& A, unsigned& S) {
        A = *(const uint4*)&canvas[r][cb];
        S = __shfl_down_sync(0xffffffffu, A.x, 1);   // lane g+1's halves 8g+8,8g+9
        if (g == 31) S = *(const unsigned*)&canvas[r][256]; // idx 256 + border 257
    };

    uint4 a0, a1; unsigned e0, e1;
    load_row(base,     a0, e0);
    load_row(base + 1, a1, e1);

    #pragma unroll
    for (int k = 0; k < 4; k++) {
        uint4 a2; unsigned e2;
        load_row(base + k + 2, a2, e2);

        uint4 V;                           // vertical 3-max
        V.x = hmax2u(hmax2u(a0.x, a1.x), a2.x);
        V.y = hmax2u(hmax2u(a0.y, a1.y), a2.y);
        V.z = hmax2u(hmax2u(a0.z, a1.z), a2.z);
        V.w = hmax2u(hmax2u(a0.w, a1.w), a2.w);
        unsigned Ve = hmax2u(hmax2u(e0, e1), e2);

        unsigned s0 = __byte_perm(V.x, V.y, 0x5432);   // (h1,h2)
        unsigned s1 = __byte_perm(V.y, V.z, 0x5432);
        unsigned s2 = __byte_perm(V.z, V.w, 0x5432);
        unsigned s3 = __byte_perm(V.w, Ve,  0x5432);
        unsigned o0 = hmax2u(V.x, hmax2u(s0, V.y));
        unsigned o1 = hmax2u(V.y, hmax2u(s1, V.z));
        unsigned o2 = hmax2u(V.z, hmax2u(s2, V.w));
        unsigned o3 = hmax2u(V.w, hmax2u(s3, Ve));

        float2 f0 = __half22float2(*(__half2*)&o0);
        float2 f1 = __half22float2(*(__half2*)&o1);
        float2 f2 = __half22float2(*(__half2*)&o2);
        float2 f3 = __half22float2(*(__half2*)&o3);

        asm volatile(
            "st.global.v8.f32 [%0], {%1, %2, %3, %4, %5, %6, %7, %8};"
            :: "l"(ob + k * WW),
               "f"(f0.x), "f"(f0.y), "f"(f1.x), "f"(f1.y),
               "f"(f2.x), "f"(f2.y), "f"(f3.x), "f"(f3.y)
            : "memory");

        a0 = a1; e0 = e1; a1 = a2; e1 = e2;
    }
}

extern "C" void kernel_launch(void* const* d_in, const int* in_sizes, int n_in,
                              void* d_out, int out_size)
{
    const float* f    = (const float*)d_in[0];
    const int*   prov = (const int*)  d_in[1];
    float* out = (float*)d_out;
    morph_unpool_dilate_kernel<<<1024 * NT, NTHR>>>(f, prov, out);
}

// round 13
// speedup vs baseline: 1.0294x; 1.0294x over previous
#include <cuda_runtime.h>
#include <cuda_fp16.h>

// B=16, C=64, H=W=256, STRIDE=2, IN_KS=OUT_KS=3
#define HH 256
#define WW 256
#define HP 128
#define WP 128
#define TH 32              // output rows per block
#define NT 8               // tiles per plane
#define CAN_H 34           // image rows R0-1 .. R0+32
#define CAN_WH 264         // halves per row (258 used; 528B, 16B-aligned stride)
#define PR_H 19            // prov rows I0-1 .. I0+17
#define PR_W 136           // ushort; cell j at index j+4, halos at 3 and 132

#define HNEG 0xFC00u           // half -inf
#define HNEG4 0xFC00FC00u

__device__ __forceinline__ unsigned hmax2u(unsigned a, unsigned b) {
    __half2 r = __hmax2(*(__half2*)&a, *(__half2*)&b);
    return *(unsigned*)&r;
}

__global__ __launch_bounds__(256, 8)
void morph_unpool_dilate_kernel(const float* __restrict__ f,
                                const int*   __restrict__ prov,
                                float*       __restrict__ out)
{
    __shared__ __align__(16) unsigned short canvas[CAN_H][CAN_WH];
    __shared__ unsigned short               sprov[PR_H][PR_W];

    const int bid  = blockIdx.x;
    const int bc   = bid >> 3;            // plane (b*c)
    const int tile = bid & 7;
    const int R0   = tile * TH;
    const int I0   = tile * (TH / 2);
    const int tid  = threadIdx.x;

    const float4* fb4 = (const float4*)(f + (size_t)bc * (HP * WP));
    const int4*   pb4 = (const int4*)  (prov + (size_t)bc * (HP * WP));

    // ---- Phase 1a: fill canvas: half(0); out-of-plane rows: half(-inf) ----
    {
        uint4* c4 = (uint4*)&canvas[0][0];
        #pragma unroll
        for (int idx = tid; idx < CAN_H * (CAN_WH / 8); idx += 256) {
            int  row  = idx / (CAN_WH / 8);
            bool ninf = (tile == 0 && row == 0) ||
                        (tile == NT - 1 && row == CAN_H - 1);
            unsigned v = ninf ? HNEG4 : 0u;
            c4[idx] = make_uint4(v, v, v, v);
        }
    }

    // ---- Phase 1b: stage provenance as u16 (int4 loads, ushort4 stores) ----
    for (int idx = tid; idx < PR_H * 32; idx += 256) {
        int li = idx >> 5;                 // cell row i = I0-1+li
        int g  = idx & 31;
        int i  = I0 - 1 + li;
        ushort4 s = make_ushort4(0, 0, 0, 0);   // out-of-range sentinel
        if ((unsigned)i < HP) {
            int4 p = __ldg(&pb4[i * 32 + g]);
            s = make_ushort4((unsigned short)p.x, (unsigned short)p.y,
                             (unsigned short)p.z, (unsigned short)p.w);
        }
        *(ushort4*)&sprov[li][(g << 2) + 4] = s;
    }
    if (tid < PR_H * 2) {                  // column halos
        int li = tid >> 1;
        if (tid & 1) sprov[li][132] = 0;        // j=128 (comparers have c>=254)
        else         sprov[li][3]   = 0xFFFF;   // j=-1  (comparers have c<=2)
    }
    __syncthreads();

    // ---- Phase 2a: -inf column borders (never scatter targets) ----
    if (tid < CAN_H * 2) {
        int r = tid >> 1;
        canvas[r][(tid & 1) ? 257 : 0] = (unsigned short)HNEG;
    }

    // ---- Phase 2b: race-free last-write-wins scatter (R3/R6 form, STS.16) ----
    // Cell (i,j) writes iff none of (i,j+1),(i+1,j-1),(i+1,j),(i+1,j+1)
    // (all higher linear index) targets the same pixel. f is loaded only if
    // at least one of the 4 cells will actually write (halo rows mostly skip).
    for (int idx = tid; idx < 18 * 32; idx += 256) {
        int li = idx >> 5;
        int g  = idx & 31;
        int i  = I0 - 1 + li;
        if ((unsigned)i < HP) {
            int j = g << 2;
            ushort4 o  = *(const ushort4*)&sprov[li][j + 4];
            ushort4 bw = *(const ushort4*)&sprov[li + 1][j + 4];
            int rr = sprov[li][j + 8];
            int bl = sprov[li + 1][j + 3];
            int br = sprov[li + 1][j + 8];
            int t0 = o.x,  t1 = o.y,  t2 = o.z,  t3 = o.w;
            int b0 = bw.x, b1 = bw.y, b2 = bw.z, b3 = bw.w;

            bool w0, w1, w2, w3;
            int  l0, l1, l2, l3;
            #define LIVE(t, n1, n2, n3, n4, wv, lv)                          \
            {                                                                \
                bool sup = ((n1) == (t)) | ((n2) == (t)) |                   \
                           ((n3) == (t)) | ((n4) == (t));                    \
                lv = ((t) >> 8) - R0 + 1;                                    \
                wv = !sup && (unsigned)lv < CAN_H;                           \
            }
            LIVE(t0, t1, bl, b0, b1, w0, l0);
            LIVE(t1, t2, b0, b1, b2, w1, l1);
            LIVE(t2, t3, b1, b2, b3, w2, l2);
            LIVE(t3, rr, b2, b3, br, w3, l3);
            #undef LIVE

            if (w0 | w1 | w2 | w3) {
                float4 fv = __ldg(&fb4[i * 32 + g]);
                if (w0) canvas[l0][(t0 & 255) + 1] =
                            __half_as_ushort(__float2half_rn(fv.x));
                if (w1) canvas[l1][(t1 & 255) + 1] =
                            __half_as_ushort(__float2half_rn(fv.y));
                if (w2) canvas[l2][(t2 & 255) + 1] =
                            __half_as_ushort(__float2half_rn(fv.z));
                if (w3) canvas[l3][(t3 & 255) + 1] =
                            __half_as_ushort(__float2half_rn(fv.w));
            }
        }
    }
    __syncthreads();

    // ---- Phase 3: 3x3 max; dense LDS.128 rows, seam via shfl of A.x,
    //      vertical HMAX2 then PRMT horizontal, streaming v8 store ----
    const int g    = tid & 31;
    const int cb   = g << 3;               // output col base; canvas idx cb..cb+9
    const int base = (tid >> 5) << 2;      // local output row base
    float* ob = out + (size_t)bc * (HH * WW) + (size_t)(R0 + base) * WW + cb;

    auto load_row = [&](int r, uint4& A, unsigned& S) {
        A = *(const uint4*)&canvas[r][cb];
        S = __shfl_down_sync(0xffffffffu, A.x, 1);   // lane g+1's halves 8g+8,8g+9
        if (g == 31) S = *(const unsigned*)&canvas[r][256]; // idx 256 + border 257
    };

    uint4 a0, a1; unsigned e0, e1;
    load_row(base,     a0, e0);
    load_row(base + 1, a1, e1);

    #pragma unroll
    for (int k = 0; k < 4; k++) {
        uint4 a2; unsigned e2;
        load_row(base + k + 2, a2, e2);

        uint4 V;                           // vertical 3-max
        V.x = hmax2u(hmax2u(a0.x, a1.x), a2.x);
        V.y = hmax2u(hmax2u(a0.y, a1.y), a2.y);
        V.z = hmax2u(hmax2u(a0.z, a1.z), a2.z);
        V.w = hmax2u(hmax2u(a0.w, a1.w), a2.w);
        unsigned Ve = hmax2u(hmax2u(e0, e1), e2);

        unsigned s0 = __byte_perm(V.x, V.y, 0x5432);   // (h1,h2)
        unsigned s1 = __byte_perm(V.y, V.z, 0x5432);
        unsigned s2 = __byte_perm(V.z, V.w, 0x5432);
        unsigned s3 = __byte_perm(V.w, Ve,  0x5432);
        unsigned o0 = hmax2u(V.x, hmax2u(s0, V.y));
        unsigned o1 = hmax2u(V.y, hmax2u(s1, V.z));
        unsigned o2 = hmax2u(V.z, hmax2u(s2, V.w));
        unsigned o3 = hmax2u(V.w, hmax2u(s3, Ve));

        float2 f0 = __half22float2(*(__half2*)&o0);
        float2 f1 = __half22float2(*(__half2*)&o1);
        float2 f2 = __half22float2(*(__half2*)&o2);
        float2 f3 = __half22float2(*(__half2*)&o3);

        asm volatile(
            "st.global.cs.v8.f32 [%0], {%1, %2, %3, %4, %5, %6, %7, %8};"
            :: "l"(ob + k * WW),
               "f"(f0.x), "f"(f0.y), "f"(f1.x), "f"(f1.y),
               "f"(f2.x), "f"(f2.y), "f"(f3.x), "f"(f3.y)
            : "memory");

        a0 = a1; e0 = e1; a1 = a2; e1 = e2;
    }
}

extern "C" void kernel_launch(void* const* d_in, const int* in_sizes, int n_in,
                              void* d_out, int out_size)
{
    const float* f    = (const float*)d_in[0];
    const int*   prov = (const int*)  d_in[1];
    float* out = (float*)d_out;
    morph_unpool_dilate_kernel<<<1024 * NT, 256>>>(f, prov, out);
}